// round 10
// baseline (speedup 1.0000x reference)
#include <cuda_runtime.h>
#include <cuda_fp16.h>
#include <cstdint>
#include <math.h>

// ---------------- problem constants ----------------
constexpr int N_TOK  = 8192;
constexpr int QH     = 32;
constexpr int KH     = 2;
constexpr int G      = 16;
constexpr int D      = 128;
constexpr int KS     = 32;
constexpr int STRIDE = 16;
constexpr int M_BLK  = (N_TOK - KS) / STRIDE + 1;  // 511
constexpr float SM_SCALE = 0.08838834764831845f;

constexpr int NB      = 8;                  // tokens per CTA (1 per warp)
constexpr int THREADS = NB * 32;            // 256
constexpr int NTILES  = 16;                 // m-tiles of 32 covering 512
constexpr int KF_U32  = NTILES * 2048;      // per kh: [tile][ni4][kp4][lane32][4]
constexpr int VF_U32  = NTILES * 2048;      // per kh: [tile][ni16][lane32][4]

// scratch (allocation-free rule: device globals)
__device__ float    g_ck [KH * M_BLK * D];
__device__ float    g_cv [KH * M_BLK * D];
__device__ uint32_t g_ckf[KH * KF_U32];     // QK B-fragments (half2, LDG.128-packed)
__device__ uint32_t g_cvf[KH * VF_U32];     // PV B-fragments (half2, LDG.128-packed)

__device__ __forceinline__ int mn_of(int n) {
    return (n >= KS - 1) ? ((n - (KS - 1)) / STRIDE + 1) : 0;
}
__device__ __forceinline__ uint32_t pack_h2(float a, float b) {
    __half2 h = __floats2half2_rn(a, b);
    return *reinterpret_cast<uint32_t*>(&h);
}
__device__ __forceinline__ uint32_t smem_u32(const void* p) {
    uint32_t a;
    asm("{ .reg .u64 t; cvta.to.shared.u64 t, %1; cvt.u32.u64 %0, t; }" : "=r"(a) : "l"(p));
    return a;
}
__device__ __forceinline__ void cp_async16(uint32_t saddr, const void* gaddr) {
    asm volatile("cp.async.cg.shared.global [%0], [%1], 16;" :: "r"(saddr), "l"(gaddr));
}
__device__ __forceinline__ void cp_commit() {
    asm volatile("cp.async.commit_group;");
}
template <int N>
__device__ __forceinline__ void cp_wait() {
    asm volatile("cp.async.wait_group %0;" :: "n"(N));
}
__device__ __forceinline__ void mma_16816(float* c,
                                          uint32_t a0, uint32_t a1, uint32_t a2, uint32_t a3,
                                          uint32_t b0, uint32_t b1) {
    asm volatile("mma.sync.aligned.m16n8k16.row.col.f32.f16.f16.f32 "
                 "{%0,%1,%2,%3}, {%4,%5,%6,%7}, {%8,%9}, {%0,%1,%2,%3};"
                 : "+f"(c[0]), "+f"(c[1]), "+f"(c[2]), "+f"(c[3])
                 : "r"(a0), "r"(a1), "r"(a2), "r"(a3), "r"(b0), "r"(b1));
}

// ---------------- kernel 1: compression ----------------
__global__ void __launch_bounds__(128) compress_kernel(
    const float* __restrict__ k, const float* __restrict__ v,
    const float* __restrict__ weight, const float* __restrict__ pe)
{
    const int m  = blockIdx.x;
    const int kh = blockIdx.y;
    const int d  = threadIdx.x;

    __shared__ float w_s[KS];
    __shared__ float wsum_s;
    if (threadIdx.x < KS) w_s[threadIdx.x] = weight[threadIdx.x];
    __syncthreads();
    if (threadIdx.x == 0) {
        float s = 0.f;
        #pragma unroll
        for (int i = 0; i < KS; i++) s += w_s[i];
        wsum_s = fmaxf(s, 1e-6f);
    }
    __syncthreads();

    float acck = 0.f, accv = 0.f;
    const int base = m * STRIDE;
    #pragma unroll 8
    for (int kk = 0; kk < KS; kk++) {
        const float w  = w_s[kk];
        const float pv = pe[kk * D + d];
        acck = fmaf(k[((size_t)(base + kk) * KH + kh) * D + d] + pv, w, acck);
        accv = fmaf(v[((size_t)(base + kk) * KH + kh) * D + d] + pv, w, accv);
    }
    const float inv = 1.0f / wsum_s;
    g_ck[((size_t)kh * M_BLK + m) * D + d] = acck * inv;
    g_cv[((size_t)kh * M_BLK + m) * D + d] = accv * inv;
}

// ---------------- kernel 2: pack fragments (LDG.128-friendly) ----------------
__global__ void __launch_bounds__(256) pack_kernel()
{
    const int i = blockIdx.x * 256 + threadIdx.x;
    if (i < KH * KF_U32) {
        // K frag: [kh][tile(16)][ni(4)][kp(4)][lane(32)][q(4)] ; ki = kp*2 + (q>>1)
        const int q    = i & 3;
        const int lane = (i >> 2) & 31;
        const int kp   = (i >> 7) & 3;
        const int ni   = (i >> 9) & 3;
        const int tile = (i >> 11) & 15;
        const int kh   = (i >> 15) & 1;
        const int ki   = kp * 2 + (q >> 1);
        const int reg  = q & 1;
        const int m = tile * 32 + ni * 8 + (lane >> 2);
        const int d = ki * 16 + reg * 8 + (lane & 3) * 2;
        float2 f = make_float2(0.f, 0.f);
        if (m < M_BLK)
            f = *reinterpret_cast<const float2*>(&g_ck[((size_t)kh * M_BLK + m) * D + d]);
        g_ckf[i] = pack_h2(f.x, f.y);
    } else {
        // V frag: [kh][tile(16)][ni(16)][lane(32)][q(4)] ; ki2 = q>>1 ; k-dim = m, n-dim = d
        const int j = i - KH * KF_U32;
        const int q    = j & 3;
        const int lane = (j >> 2) & 31;
        const int ni   = (j >> 7) & 15;
        const int tile = (j >> 11) & 15;
        const int kh   = (j >> 15) & 1;
        const int ki2  = q >> 1;
        const int reg  = q & 1;
        const int dn = ni * 8 + (lane >> 2);
        const int m  = tile * 32 + ki2 * 16 + reg * 8 + (lane & 3) * 2;
        float a = 0.f, b = 0.f;
        if (m < M_BLK)     a = g_cv[((size_t)kh * M_BLK + m) * D + dn];
        if (m + 1 < M_BLK) b = g_cv[((size_t)kh * M_BLK + m + 1) * D + dn];
        g_cvf[j] = pack_h2(a, b);
    }
}

// ---------------- kernel 3: HMMA flash attention, depth-3 cp.async ring ----------------
__global__ void __launch_bounds__(THREADS, 2) attn_mma(
    const float* __restrict__ q, float* __restrict__ out)
{
    const int bid   = blockIdx.x;
    const int kh    = bid & 1;
    const int chunk = bid >> 1;
    const int n0    = N_TOK - NB - chunk * NB;   // heavy tokens first

    const int tid  = threadIdx.x;
    const int w    = tid >> 5;
    const int lane = tid & 31;
    const int gid  = lane >> 2;
    const int tig  = lane & 3;

    const int n      = n0 + w;
    const int Mn     = mn_of(n);
    const int Mn_max = mn_of(n0 + NB - 1);   // uniform per CTA

    if (Mn_max == 0) {
        #pragma unroll
        for (int rh = 0; rh < 2; rh++) {
            float* orow = &out[(((size_t)n * QH) + kh * G + gid + 8 * rh) * D];
            const float2 z = make_float2(0.f, 0.f);
            #pragma unroll
            for (int ni = 0; ni < 16; ni++)
                *reinterpret_cast<float2*>(&orow[ni * 8 + 2 * tig]) = z;
        }
        return;
    }

    // smem: qf (32 KB) + depth-3 K/V frag ring (3 x 16 KB) = 80 KB
    __shared__ uint32_t qsm[NB * 1024];
    __shared__ uint32_t kbuf[3][2048];
    __shared__ uint32_t vbuf[3][2048];

    const uint32_t* kf = &g_ckf[(size_t)kh * KF_U32];
    const uint32_t* vf = &g_cvf[(size_t)kh * VF_U32];

    const int ntiles = (Mn_max + 31) >> 5;

    // stage one tile's K+V frags (16 KB) with 256 threads: 4 cp.async16 each
    auto stage = [&](int tile, int slot) {
        const uint32_t sk = smem_u32(&kbuf[slot][0]) + tid * 16;
        const uint32_t sv = smem_u32(&vbuf[slot][0]) + tid * 16;
        const uint32_t* gk = kf + tile * 2048 + tid * 4;
        const uint32_t* gv = vf + tile * 2048 + tid * 4;
        cp_async16(sk,        gk);
        cp_async16(sk + 4096, gk + 1024);
        cp_async16(sv,        gv);
        cp_async16(sv + 4096, gv + 1024);
    };

    // preamble: prefetch tiles 0 and 1 (group per tile; empty group if absent)
    stage(0, 0); cp_commit();
    if (ntiles > 1) stage(1, 1);
    cp_commit();

    // ---- stage Q A-fragments into warp-private smem (overlaps prefetch) ----
    uint32_t* myq = &qsm[w * 1024];
    #pragma unroll
    for (int ki = 0; ki < 8; ki++) {
        #pragma unroll
        for (int reg = 0; reg < 4; reg++) {
            const int g = gid + 8 * (reg & 1);
            const int c = 16 * ki + 8 * (reg >> 1) + 2 * tig;
            const float2 f = *reinterpret_cast<const float2*>(
                &q[(((size_t)n * QH) + kh * G + g) * D + c]);
            myq[ki * 128 + lane * 4 + reg] = pack_h2(f.x * SM_SCALE, f.y * SM_SCALE);
        }
    }

    float oacc[16][4];
    #pragma unroll
    for (int a = 0; a < 16; a++)
        #pragma unroll
        for (int c = 0; c < 4; c++) oacc[a][c] = 0.f;

    float rs[2] = {0.f, 0.f};

    for (int t = 0; t < ntiles; t++) {
        // group sequence: g0=tile0, g1=tile1, then one group per iteration.
        // wait<1>: everything except the newest group is done => tile t landed.
        cp_wait<1>();
        __syncthreads();   // tile t visible to all; all warps retired tile t-1

        // prefetch tile t+2 into slot (t+2)%3 (last read at tile t-1 -> safe);
        // always commit to keep the group count uniform.
        if (t + 2 < ntiles) stage(t + 2, (t + 2) % 3);
        cp_commit();

        const int vcnt = Mn - (t << 5);
        if (vcnt > 0) {
            const uint32_t* kb = &kbuf[t % 3][0];
            const uint32_t* vb = &vbuf[t % 3][0];

            // ---- QK: S[16 x 32] ----
            float sacc[4][4];
            #pragma unroll
            for (int a = 0; a < 4; a++)
                #pragma unroll
                for (int c = 0; c < 4; c++) sacc[a][c] = 0.f;

            #pragma unroll
            for (int kp = 0; kp < 4; kp++) {
                const uint4 a0 = *reinterpret_cast<const uint4*>(&myq[(2 * kp    ) * 128 + lane * 4]);
                const uint4 a1 = *reinterpret_cast<const uint4*>(&myq[(2 * kp + 1) * 128 + lane * 4]);
                #pragma unroll
                for (int ni = 0; ni < 4; ni++) {
                    const uint4 b = *reinterpret_cast<const uint4*>(&kb[((ni * 4 + kp) << 7) + lane * 4]);
                    mma_16816(sacc[ni], a0.x, a0.y, a0.z, a0.w, b.x, b.y);
                    mma_16816(sacc[ni], a1.x, a1.y, a1.z, a1.w, b.z, b.w);
                }
            }

            // ---- softmax (fixed base), pack P into A-fragments ----
            uint32_t pf[2][4];
            #pragma unroll
            for (int ni = 0; ni < 4; ni++) {
                const int col = ni * 8 + 2 * tig;
                const bool v0 = col     < vcnt;
                const bool v1 = col + 1 < vcnt;
                const float p0 = v0 ? __expf(sacc[ni][0] - 5.0f) : 0.f;
                const float p1 = v1 ? __expf(sacc[ni][1] - 5.0f) : 0.f;
                const float p2 = v0 ? __expf(sacc[ni][2] - 5.0f) : 0.f;
                const float p3 = v1 ? __expf(sacc[ni][3] - 5.0f) : 0.f;
                rs[0] += p0 + p1;
                rs[1] += p2 + p3;
                const int ki2 = ni >> 1, ch = ni & 1;
                pf[ki2][0 + 2 * ch] = pack_h2(p0, p1);
                pf[ki2][1 + 2 * ch] = pack_h2(p2, p3);
            }

            // ---- PV: O[16 x 128] += P @ CV ----
            #pragma unroll
            for (int ni = 0; ni < 16; ni++) {
                const uint4 b = *reinterpret_cast<const uint4*>(&vb[(ni << 7) + lane * 4]);
                mma_16816(oacc[ni], pf[0][0], pf[0][1], pf[0][2], pf[0][3], b.x, b.y);
                mma_16816(oacc[ni], pf[1][0], pf[1][1], pf[1][2], pf[1][3], b.z, b.w);
            }
        }
    }

    // ---- epilogue ----
    #pragma unroll
    for (int rh = 0; rh < 2; rh++) {
        float s = rs[rh];
        s += __shfl_xor_sync(0xffffffffu, s, 1);
        s += __shfl_xor_sync(0xffffffffu, s, 2);
        const float inv = (Mn > 0) ? (1.0f / s) : 0.f;
        float* orow = &out[(((size_t)n * QH) + kh * G + gid + 8 * rh) * D];
        #pragma unroll
        for (int ni = 0; ni < 16; ni++) {
            float2 o;
            o.x = oacc[ni][2 * rh + 0] * inv;
            o.y = oacc[ni][2 * rh + 1] * inv;
            *reinterpret_cast<float2*>(&orow[ni * 8 + 2 * tig]) = o;
        }
    }
}

// ---------------- launch ----------------
extern "C" void kernel_launch(void* const* d_in, const int* in_sizes, int n_in,
                              void* d_out, int out_size)
{
    const float* q  = (const float*)d_in[0];
    const float* k  = (const float*)d_in[1];
    const float* v  = (const float*)d_in[2];
    const float* w  = (const float*)d_in[3];
    const float* pe = (const float*)d_in[4];
    float* out = (float*)d_out;

    dim3 cgrid(M_BLK, KH);
    compress_kernel<<<cgrid, 128>>>(k, v, w, pe);
    pack_kernel<<<(KH * (KF_U32 + VF_U32)) / 256, 256>>>();
    attn_mma<<<(N_TOK / NB) * KH, THREADS>>>(q, out);
}

// round 11
// speedup vs baseline: 1.0366x; 1.0366x over previous
#include <cuda_runtime.h>
#include <cuda_fp16.h>
#include <cstdint>
#include <math.h>

// ---------------- problem constants ----------------
constexpr int N_TOK  = 8192;
constexpr int QH     = 32;
constexpr int KH     = 2;
constexpr int G      = 16;
constexpr int D      = 128;
constexpr int KS     = 32;
constexpr int STRIDE = 16;
constexpr int M_BLK  = (N_TOK - KS) / STRIDE + 1;  // 511
constexpr float SM_SCALE = 0.08838834764831845f;

constexpr int NB      = 4;                  // tokens per CTA (1 per warp)
constexpr int NTILES  = 16;                 // m-tiles of 32 covering 512
constexpr int KF_U32  = NTILES * 2048;      // per kh: [tile][ni4][kp4][lane32][4]
constexpr int VF_U32  = NTILES * 2048;      // per kh: [tile][ni16][lane32][4]

// scratch (allocation-free rule: device globals)
__device__ float    g_ck [KH * M_BLK * D];
__device__ float    g_cv [KH * M_BLK * D];
__device__ uint32_t g_ckf[KH * KF_U32];     // QK B-fragments (half2, LDG.128-packed)
__device__ uint32_t g_cvf[KH * VF_U32];     // PV B-fragments (half2, LDG.128-packed)

__device__ __forceinline__ int mn_of(int n) {
    return (n >= KS - 1) ? ((n - (KS - 1)) / STRIDE + 1) : 0;
}
__device__ __forceinline__ uint32_t pack_h2(float a, float b) {
    __half2 h = __floats2half2_rn(a, b);
    return *reinterpret_cast<uint32_t*>(&h);
}
__device__ __forceinline__ uint32_t smem_u32(const void* p) {
    uint32_t a;
    asm("{ .reg .u64 t; cvta.to.shared.u64 t, %1; cvt.u32.u64 %0, t; }" : "=r"(a) : "l"(p));
    return a;
}
__device__ __forceinline__ void cp_async16(uint32_t saddr, const void* gaddr) {
    asm volatile("cp.async.cg.shared.global [%0], [%1], 16;" :: "r"(saddr), "l"(gaddr));
}
__device__ __forceinline__ void cp_commit() {
    asm volatile("cp.async.commit_group;");
}
template <int N>
__device__ __forceinline__ void cp_wait() {
    asm volatile("cp.async.wait_group %0;" :: "n"(N));
}
__device__ __forceinline__ void mma_16816(float* c,
                                          uint32_t a0, uint32_t a1, uint32_t a2, uint32_t a3,
                                          uint32_t b0, uint32_t b1) {
    asm volatile("mma.sync.aligned.m16n8k16.row.col.f32.f16.f16.f32 "
                 "{%0,%1,%2,%3}, {%4,%5,%6,%7}, {%8,%9}, {%0,%1,%2,%3};"
                 : "+f"(c[0]), "+f"(c[1]), "+f"(c[2]), "+f"(c[3])
                 : "r"(a0), "r"(a1), "r"(a2), "r"(a3), "r"(b0), "r"(b1));
}

// ---------------- kernel 1: compression ----------------
__global__ void __launch_bounds__(128) compress_kernel(
    const float* __restrict__ k, const float* __restrict__ v,
    const float* __restrict__ weight, const float* __restrict__ pe)
{
    const int m  = blockIdx.x;
    const int kh = blockIdx.y;
    const int d  = threadIdx.x;

    __shared__ float w_s[KS];
    __shared__ float wsum_s;
    if (threadIdx.x < KS) w_s[threadIdx.x] = weight[threadIdx.x];
    __syncthreads();
    if (threadIdx.x == 0) {
        float s = 0.f;
        #pragma unroll
        for (int i = 0; i < KS; i++) s += w_s[i];
        wsum_s = fmaxf(s, 1e-6f);
    }
    __syncthreads();

    float acck = 0.f, accv = 0.f;
    const int base = m * STRIDE;
    #pragma unroll 8
    for (int kk = 0; kk < KS; kk++) {
        const float w  = w_s[kk];
        const float pv = pe[kk * D + d];
        acck = fmaf(k[((size_t)(base + kk) * KH + kh) * D + d] + pv, w, acck);
        accv = fmaf(v[((size_t)(base + kk) * KH + kh) * D + d] + pv, w, accv);
    }
    const float inv = 1.0f / wsum_s;
    g_ck[((size_t)kh * M_BLK + m) * D + d] = acck * inv;
    g_cv[((size_t)kh * M_BLK + m) * D + d] = accv * inv;
}

// ---------------- kernel 2: pack fragments (LDG.128-friendly) ----------------
__global__ void __launch_bounds__(256) pack_kernel()
{
    const int i = blockIdx.x * 256 + threadIdx.x;
    if (i < KH * KF_U32) {
        // K frag: [kh][tile(16)][ni(4)][kp(4)][lane(32)][q(4)] ; ki = kp*2 + (q>>1)
        const int q    = i & 3;
        const int lane = (i >> 2) & 31;
        const int kp   = (i >> 7) & 3;
        const int ni   = (i >> 9) & 3;
        const int tile = (i >> 11) & 15;
        const int kh   = (i >> 15) & 1;
        const int ki   = kp * 2 + (q >> 1);
        const int reg  = q & 1;
        const int m = tile * 32 + ni * 8 + (lane >> 2);
        const int d = ki * 16 + reg * 8 + (lane & 3) * 2;
        float2 f = make_float2(0.f, 0.f);
        if (m < M_BLK)
            f = *reinterpret_cast<const float2*>(&g_ck[((size_t)kh * M_BLK + m) * D + d]);
        g_ckf[i] = pack_h2(f.x, f.y);
    } else {
        // V frag: [kh][tile(16)][ni(16)][lane(32)][q(4)] ; ki2 = q>>1 ; k-dim = m, n-dim = d
        const int j = i - KH * KF_U32;
        const int q    = j & 3;
        const int lane = (j >> 2) & 31;
        const int ni   = (j >> 7) & 15;
        const int tile = (j >> 11) & 15;
        const int kh   = (j >> 15) & 1;
        const int ki2  = q >> 1;
        const int reg  = q & 1;
        const int dn = ni * 8 + (lane >> 2);
        const int m  = tile * 32 + ki2 * 16 + reg * 8 + (lane & 3) * 2;
        float a = 0.f, b = 0.f;
        if (m < M_BLK)     a = g_cv[((size_t)kh * M_BLK + m) * D + dn];
        if (m + 1 < M_BLK) b = g_cv[((size_t)kh * M_BLK + m + 1) * D + dn];
        g_cvf[j] = pack_h2(a, b);
    }
}

// ---------------- kernel 3: HMMA flash attention, single-barrier double buffer ----------------
__global__ void __launch_bounds__(128, 4) attn_mma(
    const float* __restrict__ q, float* __restrict__ out)
{
    const int bid   = blockIdx.x;
    const int kh    = bid & 1;
    const int chunk = bid >> 1;
    const int n0    = N_TOK - NB - chunk * NB;   // heavy tokens first

    const int tid  = threadIdx.x;
    const int w    = tid >> 5;
    const int lane = tid & 31;
    const int gid  = lane >> 2;
    const int tig  = lane & 3;

    const int n      = n0 + w;
    const int Mn     = mn_of(n);
    const int Mn_max = mn_of(n0 + NB - 1);   // uniform per CTA

    if (Mn_max == 0) {
        #pragma unroll
        for (int rh = 0; rh < 2; rh++) {
            float* orow = &out[(((size_t)n * QH) + kh * G + gid + 8 * rh) * D];
            const float2 z = make_float2(0.f, 0.f);
            #pragma unroll
            for (int ni = 0; ni < 16; ni++)
                *reinterpret_cast<float2*>(&orow[ni * 8 + 2 * tig]) = z;
        }
        return;
    }

    // smem: qf (16 KB) + double-buffered K/V frag tiles (2 x 16 KB) = 48 KB
    __shared__ uint32_t qsm[NB * 1024];
    __shared__ uint32_t kbuf[2][2048];
    __shared__ uint32_t vbuf[2][2048];

    const uint32_t* kf = &g_ckf[(size_t)kh * KF_U32];
    const uint32_t* vf = &g_cvf[(size_t)kh * VF_U32];

    const int ntiles = (Mn_max + 31) >> 5;

    // stage one tile's K+V frags (16 KB) with 128 threads: 8 cp.async16 each
    auto stage = [&](int tile, int slot) {
        const uint32_t sk = smem_u32(&kbuf[slot][0]) + tid * 16;
        const uint32_t sv = smem_u32(&vbuf[slot][0]) + tid * 16;
        const uint32_t* gk = kf + tile * 2048 + tid * 4;
        const uint32_t* gv = vf + tile * 2048 + tid * 4;
        #pragma unroll
        for (int i = 0; i < 4; i++) {
            cp_async16(sk + i * 2048, gk + i * 512);
            cp_async16(sv + i * 2048, gv + i * 512);
        }
    };

    // preamble: prefetch tile 0
    stage(0, 0);
    cp_commit();

    // ---- stage Q A-fragments into warp-private smem (overlaps prefetch) ----
    uint32_t* myq = &qsm[w * 1024];
    #pragma unroll
    for (int ki = 0; ki < 8; ki++) {
        #pragma unroll
        for (int reg = 0; reg < 4; reg++) {
            const int g = gid + 8 * (reg & 1);
            const int c = 16 * ki + 8 * (reg >> 1) + 2 * tig;
            const float2 f = *reinterpret_cast<const float2*>(
                &q[(((size_t)n * QH) + kh * G + g) * D + c]);
            myq[ki * 128 + lane * 4 + reg] = pack_h2(f.x * SM_SCALE, f.y * SM_SCALE);
        }
    }

    float oacc[16][4];
    #pragma unroll
    for (int a = 0; a < 16; a++)
        #pragma unroll
        for (int c = 0; c < 4; c++) oacc[a][c] = 0.f;

    float rs[2] = {0.f, 0.f};

    for (int t = 0; t < ntiles; t++) {
        cp_wait<0>();      // my groups for tile t retired
        __syncthreads();   // everyone's tile t staged; everyone done computing t-1

        // prefetch t+1 into the slot that held t-1 (all reads retired by barrier)
        if (t + 1 < ntiles) {
            stage(t + 1, (t + 1) & 1);
            cp_commit();
        }

        const int vcnt = Mn - (t << 5);
        if (vcnt > 0) {
            const uint32_t* kb = &kbuf[t & 1][0];
            const uint32_t* vb = &vbuf[t & 1][0];

            // ---- QK: S[16 x 32] ----
            float sacc[4][4];
            #pragma unroll
            for (int a = 0; a < 4; a++)
                #pragma unroll
                for (int c = 0; c < 4; c++) sacc[a][c] = 0.f;

            #pragma unroll
            for (int kp = 0; kp < 4; kp++) {
                const uint4 a0 = *reinterpret_cast<const uint4*>(&myq[(2 * kp    ) * 128 + lane * 4]);
                const uint4 a1 = *reinterpret_cast<const uint4*>(&myq[(2 * kp + 1) * 128 + lane * 4]);
                #pragma unroll
                for (int ni = 0; ni < 4; ni++) {
                    const uint4 b = *reinterpret_cast<const uint4*>(&kb[((ni * 4 + kp) << 7) + lane * 4]);
                    mma_16816(sacc[ni], a0.x, a0.y, a0.z, a0.w, b.x, b.y);
                    mma_16816(sacc[ni], a1.x, a1.y, a1.z, a1.w, b.z, b.w);
                }
            }

            // ---- softmax (fixed base), pack P into A-fragments ----
            uint32_t pf[2][4];
            #pragma unroll
            for (int ni = 0; ni < 4; ni++) {
                const int col = ni * 8 + 2 * tig;
                const bool v0 = col     < vcnt;
                const bool v1 = col + 1 < vcnt;
                const float p0 = v0 ? __expf(sacc[ni][0] - 5.0f) : 0.f;
                const float p1 = v1 ? __expf(sacc[ni][1] - 5.0f) : 0.f;
                const float p2 = v0 ? __expf(sacc[ni][2] - 5.0f) : 0.f;
                const float p3 = v1 ? __expf(sacc[ni][3] - 5.0f) : 0.f;
                rs[0] += p0 + p1;
                rs[1] += p2 + p3;
                const int ki2 = ni >> 1, ch = ni & 1;
                pf[ki2][0 + 2 * ch] = pack_h2(p0, p1);
                pf[ki2][1 + 2 * ch] = pack_h2(p2, p3);
            }

            // ---- PV: O[16 x 128] += P @ CV ----
            #pragma unroll
            for (int ni = 0; ni < 16; ni++) {
                const uint4 b = *reinterpret_cast<const uint4*>(&vb[(ni << 7) + lane * 4]);
                mma_16816(oacc[ni], pf[0][0], pf[0][1], pf[0][2], pf[0][3], b.x, b.y);
                mma_16816(oacc[ni], pf[1][0], pf[1][1], pf[1][2], pf[1][3], b.z, b.w);
            }
        }
    }

    // ---- epilogue ----
    #pragma unroll
    for (int rh = 0; rh < 2; rh++) {
        float s = rs[rh];
        s += __shfl_xor_sync(0xffffffffu, s, 1);
        s += __shfl_xor_sync(0xffffffffu, s, 2);
        const float inv = (Mn > 0) ? (1.0f / s) : 0.f;
        float* orow = &out[(((size_t)n * QH) + kh * G + gid + 8 * rh) * D];
        #pragma unroll
        for (int ni = 0; ni < 16; ni++) {
            float2 o;
            o.x = oacc[ni][2 * rh + 0] * inv;
            o.y = oacc[ni][2 * rh + 1] * inv;
            *reinterpret_cast<float2*>(&orow[ni * 8 + 2 * tig]) = o;
        }
    }
}

// ---------------- launch ----------------
extern "C" void kernel_launch(void* const* d_in, const int* in_sizes, int n_in,
                              void* d_out, int out_size)
{
    const float* q  = (const float*)d_in[0];
    const float* k  = (const float*)d_in[1];
    const float* v  = (const float*)d_in[2];
    const float* w  = (const float*)d_in[3];
    const float* pe = (const float*)d_in[4];
    float* out = (float*)d_out;

    dim3 cgrid(M_BLK, KH);
    compress_kernel<<<cgrid, 128>>>(k, v, w, pe);
    pack_kernel<<<(KH * (KF_U32 + VF_U32)) / 256, 256>>>();
    attn_mma<<<(N_TOK / NB) * KH, 128>>>(q, out);
}

// round 12
// speedup vs baseline: 1.0806x; 1.0424x over previous
#include <cuda_runtime.h>
#include <cuda_fp16.h>
#include <cstdint>
#include <math.h>

// ---------------- problem constants ----------------
constexpr int N_TOK  = 8192;
constexpr int QH     = 32;
constexpr int KH     = 2;
constexpr int G      = 16;
constexpr int D      = 128;
constexpr int KS     = 32;
constexpr int STRIDE = 16;
constexpr int M_BLK  = (N_TOK - KS) / STRIDE + 1;  // 511
constexpr float SM_SCALE = 0.08838834764831845f;

constexpr int NB      = 4;                  // tokens per CTA (1 per warp)
constexpr int NTILES  = 16;                 // m-tiles of 32 covering 512
constexpr int KF_U32  = NTILES * 2048;      // per kh: [tile][ni4][kp4][lane32][4]
constexpr int VF_U32  = NTILES * 2048;      // per kh: [tile][ni16][lane32][4]

// scratch (allocation-free rule: device globals; zero at module load, and we
// only ever write the same deterministic values -> replay-safe)
__device__ uint32_t g_ckf[KH * KF_U32];     // QK B-fragments (half2, LDG.128-packed)
__device__ uint32_t g_cvf[KH * VF_U32];     // PV B-fragments (half2, LDG.128-packed)

__device__ __forceinline__ int mn_of(int n) {
    return (n >= KS - 1) ? ((n - (KS - 1)) / STRIDE + 1) : 0;
}
__device__ __forceinline__ uint32_t pack_h2(float a, float b) {
    __half2 h = __floats2half2_rn(a, b);
    return *reinterpret_cast<uint32_t*>(&h);
}
__device__ __forceinline__ uint32_t smem_u32(const void* p) {
    uint32_t a;
    asm("{ .reg .u64 t; cvta.to.shared.u64 t, %1; cvt.u32.u64 %0, t; }" : "=r"(a) : "l"(p));
    return a;
}
__device__ __forceinline__ void cp_async16(uint32_t saddr, const void* gaddr) {
    asm volatile("cp.async.cg.shared.global [%0], [%1], 16;" :: "r"(saddr), "l"(gaddr));
}
__device__ __forceinline__ void cp_commit() {
    asm volatile("cp.async.commit_group;");
}
template <int N>
__device__ __forceinline__ void cp_wait() {
    asm volatile("cp.async.wait_group %0;" :: "n"(N));
}
__device__ __forceinline__ void mma_16816(float* c,
                                          uint32_t a0, uint32_t a1, uint32_t a2, uint32_t a3,
                                          uint32_t b0, uint32_t b1) {
    asm volatile("mma.sync.aligned.m16n8k16.row.col.f32.f16.f16.f32 "
                 "{%0,%1,%2,%3}, {%4,%5,%6,%7}, {%8,%9}, {%0,%1,%2,%3};"
                 : "+f"(c[0]), "+f"(c[1]), "+f"(c[2]), "+f"(c[3])
                 : "r"(a0), "r"(a1), "r"(a2), "r"(a3), "r"(b0), "r"(b1));
}

// ---------------- kernel 1: fused compression + fragment pack ----------------
// grid: (256, KH). block: 256 threads = 2 consecutive m-blocks x 128 d.
// Writes K frags (d,d+1 pairs via shfl) and V frags (m,m+1 pairs via smem).
__global__ void __launch_bounds__(256) compress_pack_kernel(
    const float* __restrict__ k, const float* __restrict__ v,
    const float* __restrict__ weight, const float* __restrict__ pe)
{
    const int kh = blockIdx.y;
    const int mi = threadIdx.x >> 7;        // 0/1
    const int d  = threadIdx.x & 127;
    const int m  = blockIdx.x * 2 + mi;     // 0..511 (m=511 is padding)

    __shared__ float w_s[KS];
    __shared__ float wsum_s;
    __shared__ float cvs[2][128];
    if (threadIdx.x < KS) w_s[threadIdx.x] = weight[threadIdx.x];
    __syncthreads();
    if (threadIdx.x == 0) {
        float s = 0.f;
        #pragma unroll
        for (int i = 0; i < KS; i++) s += w_s[i];
        wsum_s = fmaxf(s, 1e-6f);
    }
    __syncthreads();

    float ck = 0.f, cv = 0.f;
    if (m < M_BLK) {
        float acck = 0.f, accv = 0.f;
        const int base = m * STRIDE;
        #pragma unroll 8
        for (int kk = 0; kk < KS; kk++) {
            const float w  = w_s[kk];
            const float pv = pe[kk * D + d];
            acck = fmaf(k[((size_t)(base + kk) * KH + kh) * D + d] + pv, w, acck);
            accv = fmaf(v[((size_t)(base + kk) * KH + kh) * D + d] + pv, w, accv);
        }
        const float inv = 1.0f / wsum_s;
        ck = acck * inv;
        cv = accv * inv;
    }

    // ---- V exchange: pair (m0, m0+1) along m ----
    cvs[mi][d] = cv;

    // ---- K frag: pair (d, d+1); even-d lane pulls odd-d neighbor (same warp) ----
    const float ck1 = __shfl_down_sync(0xffffffffu, ck, 1);
    if ((d & 1) == 0) {
        const int tile = m >> 5;
        const int ni   = (m >> 3) & 3;
        const int lane = ((m & 7) << 2) | ((d >> 1) & 3);
        const int ki   = d >> 4;
        const int reg  = (d >> 3) & 1;
        const int kp   = ki >> 1;
        const int qk   = ((ki & 1) << 1) | reg;
        const int idx  = ((((kh * NTILES + tile) * 4 + ni) * 4 + kp) * 32 + lane) * 4 + qk;
        g_ckf[idx] = pack_h2(ck, ck1);
    }

    __syncthreads();

    // ---- V frag: mi==0 threads write pair (m0, m0+1) for their d ----
    if (mi == 0) {
        const int m0   = blockIdx.x * 2;    // even
        const int tile = m0 >> 5;
        const int ki2  = (m0 >> 4) & 1;
        const int reg  = (m0 >> 3) & 1;
        const int lane = ((d & 7) << 2) | ((m0 >> 1) & 3);
        const int ni   = d >> 3;
        const int qv   = (ki2 << 1) | reg;
        const int idx  = (((kh * NTILES + tile) * 16 + ni) * 32 + lane) * 4 + qv;
        g_cvf[idx] = pack_h2(cvs[0][d], cvs[1][d]);
    }
}

// ---------------- kernel 2: HMMA flash attention (round-9 pipeline + tile skip) ----------------
__global__ void __launch_bounds__(128, 4) attn_mma(
    const float* __restrict__ q, float* __restrict__ out)
{
    const int bid   = blockIdx.x;
    const int kh    = bid & 1;
    const int chunk = bid >> 1;
    const int n0    = N_TOK - NB - chunk * NB;   // heavy tokens first

    const int tid  = threadIdx.x;
    const int w    = tid >> 5;
    const int lane = tid & 31;
    const int gid  = lane >> 2;
    const int tig  = lane & 3;

    const int n      = n0 + w;
    const int Mn     = mn_of(n);
    const int Mn_max = mn_of(n0 + NB - 1);   // uniform per CTA

    if (Mn_max == 0) {
        #pragma unroll
        for (int rh = 0; rh < 2; rh++) {
            float* orow = &out[(((size_t)n * QH) + kh * G + gid + 8 * rh) * D];
            const float2 z = make_float2(0.f, 0.f);
            #pragma unroll
            for (int ni = 0; ni < 16; ni++)
                *reinterpret_cast<float2*>(&orow[ni * 8 + 2 * tig]) = z;
        }
        return;
    }

    // smem: qf (16 KB) + double-buffered K/V frag tiles (2 x 16 KB) = 48 KB
    __shared__ uint32_t qsm[NB * 1024];
    __shared__ uint32_t kbuf[2][2048];
    __shared__ uint32_t vbuf[2][2048];

    const uint32_t* kf = &g_ckf[(size_t)kh * KF_U32];
    const uint32_t* vf = &g_cvf[(size_t)kh * VF_U32];

    const int ntiles = (Mn_max + 31) >> 5;

    auto stage = [&](int tile, int slot) {
        const uint32_t sk = smem_u32(&kbuf[slot][0]) + tid * 16;
        const uint32_t sv = smem_u32(&vbuf[slot][0]) + tid * 16;
        const uint32_t* gk = kf + tile * 2048 + tid * 4;
        const uint32_t* gv = vf + tile * 2048 + tid * 4;
        #pragma unroll
        for (int i = 0; i < 4; i++) {
            cp_async16(sk + i * 2048, gk + i * 512);
            cp_async16(sv + i * 2048, gv + i * 512);
        }
    };

    // prefetch tile 0
    stage(0, 0);
    cp_commit();

    // stage Q A-fragments into warp-private smem (overlaps prefetch)
    uint32_t* myq = &qsm[w * 1024];
    #pragma unroll
    for (int ki = 0; ki < 8; ki++) {
        #pragma unroll
        for (int reg = 0; reg < 4; reg++) {
            const int g = gid + 8 * (reg & 1);
            const int c = 16 * ki + 8 * (reg >> 1) + 2 * tig;
            const float2 f = *reinterpret_cast<const float2*>(
                &q[(((size_t)n * QH) + kh * G + g) * D + c]);
            myq[ki * 128 + lane * 4 + reg] = pack_h2(f.x * SM_SCALE, f.y * SM_SCALE);
        }
    }

    float oacc[16][4];
    #pragma unroll
    for (int a = 0; a < 16; a++)
        #pragma unroll
        for (int c = 0; c < 4; c++) oacc[a][c] = 0.f;

    float rs[2] = {0.f, 0.f};

    for (int t = 0; t < ntiles; t++) {
        // prefetch next tile into alternate buffer, then wait for current
        if (t + 1 < ntiles) {
            stage(t + 1, (t + 1) & 1);
            cp_commit();
            cp_wait<1>();
        } else {
            cp_wait<0>();
        }
        __syncthreads();   // current buffer staged for all warps

        const int vcnt = Mn - (t << 5);
        if (vcnt > 0) {
            const uint32_t* kb = &kbuf[t & 1][0];
            const uint32_t* vb = &vbuf[t & 1][0];

            // ---- QK: S[16 x 32] ----
            float sacc[4][4];
            #pragma unroll
            for (int a = 0; a < 4; a++)
                #pragma unroll
                for (int c = 0; c < 4; c++) sacc[a][c] = 0.f;

            #pragma unroll
            for (int kp = 0; kp < 4; kp++) {
                const uint4 a0 = *reinterpret_cast<const uint4*>(&myq[(2 * kp    ) * 128 + lane * 4]);
                const uint4 a1 = *reinterpret_cast<const uint4*>(&myq[(2 * kp + 1) * 128 + lane * 4]);
                #pragma unroll
                for (int ni = 0; ni < 4; ni++) {
                    const uint4 b = *reinterpret_cast<const uint4*>(&kb[((ni * 4 + kp) << 7) + lane * 4]);
                    mma_16816(sacc[ni], a0.x, a0.y, a0.z, a0.w, b.x, b.y);
                    mma_16816(sacc[ni], a1.x, a1.y, a1.z, a1.w, b.z, b.w);
                }
            }

            // ---- softmax (fixed base), pack P into A-fragments ----
            uint32_t pf[2][4];
            #pragma unroll
            for (int ni = 0; ni < 4; ni++) {
                const int col = ni * 8 + 2 * tig;
                const bool v0 = col     < vcnt;
                const bool v1 = col + 1 < vcnt;
                const float p0 = v0 ? __expf(sacc[ni][0] - 5.0f) : 0.f;
                const float p1 = v1 ? __expf(sacc[ni][1] - 5.0f) : 0.f;
                const float p2 = v0 ? __expf(sacc[ni][2] - 5.0f) : 0.f;
                const float p3 = v1 ? __expf(sacc[ni][3] - 5.0f) : 0.f;
                rs[0] += p0 + p1;
                rs[1] += p2 + p3;
                const int ki2 = ni >> 1, ch = ni & 1;
                pf[ki2][0 + 2 * ch] = pack_h2(p0, p1);
                pf[ki2][1 + 2 * ch] = pack_h2(p2, p3);
            }

            // ---- PV: O[16 x 128] += P @ CV ----
            #pragma unroll
            for (int ni = 0; ni < 16; ni++) {
                const uint4 b = *reinterpret_cast<const uint4*>(&vb[(ni << 7) + lane * 4]);
                mma_16816(oacc[ni], pf[0][0], pf[0][1], pf[0][2], pf[0][3], b.x, b.y);
                mma_16816(oacc[ni], pf[1][0], pf[1][1], pf[1][2], pf[1][3], b.z, b.w);
            }
        }

        __syncthreads();   // all warps done with this buffer before restaging
    }

    // ---- epilogue ----
    #pragma unroll
    for (int rh = 0; rh < 2; rh++) {
        float s = rs[rh];
        s += __shfl_xor_sync(0xffffffffu, s, 1);
        s += __shfl_xor_sync(0xffffffffu, s, 2);
        const float inv = (Mn > 0) ? (1.0f / s) : 0.f;
        float* orow = &out[(((size_t)n * QH) + kh * G + gid + 8 * rh) * D];
        #pragma unroll
        for (int ni = 0; ni < 16; ni++) {
            float2 o;
            o.x = oacc[ni][2 * rh + 0] * inv;
            o.y = oacc[ni][2 * rh + 1] * inv;
            *reinterpret_cast<float2*>(&orow[ni * 8 + 2 * tig]) = o;
        }
    }
}

// ---------------- launch ----------------
extern "C" void kernel_launch(void* const* d_in, const int* in_sizes, int n_in,
                              void* d_out, int out_size)
{
    const float* q  = (const float*)d_in[0];
    const float* k  = (const float*)d_in[1];
    const float* v  = (const float*)d_in[2];
    const float* w  = (const float*)d_in[3];
    const float* pe = (const float*)d_in[4];
    float* out = (float*)d_out;

    dim3 cgrid(256, KH);
    compress_pack_kernel<<<cgrid, 256>>>(k, v, w, pe);
    attn_mma<<<(N_TOK / NB) * KH, 128>>>(q, out);
}

// round 13
// speedup vs baseline: 1.0860x; 1.0049x over previous
#include <cuda_runtime.h>
#include <cuda_fp16.h>
#include <cstdint>
#include <math.h>

// ---------------- problem constants ----------------
constexpr int N_TOK  = 8192;
constexpr int QH     = 32;
constexpr int KH     = 2;
constexpr int G      = 16;
constexpr int D      = 128;
constexpr int KS     = 32;
constexpr int STRIDE = 16;
constexpr int M_BLK  = (N_TOK - KS) / STRIDE + 1;  // 511
constexpr float SM_SCALE = 0.08838834764831845f;
constexpr float LOG2E    = 1.4426950408889634f;
constexpr float QSCALE   = SM_SCALE * LOG2E;       // fold log2e into q

constexpr int NB      = 4;                  // tokens per CTA (1 per warp)
constexpr int NTILES  = 16;                 // m-tiles of 32 covering 512
constexpr int KF_U32  = NTILES * 2048;      // per kh: [tile][ni4][kp4][lane32][4]
constexpr int VF_U32  = NTILES * 2048;      // per kh: [tile][ni16][lane32][4]

// scratch (allocation-free rule: device globals)
__device__ uint32_t g_ckf[KH * KF_U32];     // QK B-fragments (half2, LDG.128-packed)
__device__ uint32_t g_cvf[KH * VF_U32];     // PV B-fragments (half2, LDG.128-packed)

__device__ __forceinline__ int mn_of(int n) {
    return (n >= KS - 1) ? ((n - (KS - 1)) / STRIDE + 1) : 0;
}
__device__ __forceinline__ uint32_t pack_h2(float a, float b) {
    __half2 h = __floats2half2_rn(a, b);
    return *reinterpret_cast<uint32_t*>(&h);
}
__device__ __forceinline__ uint32_t smem_u32(const void* p) {
    uint32_t a;
    asm("{ .reg .u64 t; cvta.to.shared.u64 t, %1; cvt.u32.u64 %0, t; }" : "=r"(a) : "l"(p));
    return a;
}
__device__ __forceinline__ void cp_async16(uint32_t saddr, const void* gaddr) {
    asm volatile("cp.async.cg.shared.global [%0], [%1], 16;" :: "r"(saddr), "l"(gaddr));
}
__device__ __forceinline__ void cp_commit() {
    asm volatile("cp.async.commit_group;");
}
template <int N>
__device__ __forceinline__ void cp_wait() {
    asm volatile("cp.async.wait_group %0;" :: "n"(N));
}
__device__ __forceinline__ void mma_16816(float* c,
                                          uint32_t a0, uint32_t a1, uint32_t a2, uint32_t a3,
                                          uint32_t b0, uint32_t b1) {
    asm volatile("mma.sync.aligned.m16n8k16.row.col.f32.f16.f16.f32 "
                 "{%0,%1,%2,%3}, {%4,%5,%6,%7}, {%8,%9}, {%0,%1,%2,%3};"
                 : "+f"(c[0]), "+f"(c[1]), "+f"(c[2]), "+f"(c[3])
                 : "r"(a0), "r"(a1), "r"(a2), "r"(a3), "r"(b0), "r"(b1));
}

// ---------------- kernel 1: fused compression + fragment pack ----------------
// grid: (256, KH). block: 512 threads = role(2: k/v) x m-pair(2) x d(128).
// Each thread accumulates ONE of {k, v} over the 32-tap window (32 loads).
__global__ void __launch_bounds__(512) compress_pack_kernel(
    const float* __restrict__ k, const float* __restrict__ v,
    const float* __restrict__ weight, const float* __restrict__ pe)
{
    const int kh   = blockIdx.y;
    const int role = threadIdx.x >> 8;        // 0 = k, 1 = v
    const int mi   = (threadIdx.x >> 7) & 1;  // which m of the pair
    const int d    = threadIdx.x & 127;
    const int m    = blockIdx.x * 2 + mi;     // 0..511 (511 = padding)

    __shared__ float w_s[KS];
    __shared__ float wsum_s;
    __shared__ float cvs[2][128];
    if (threadIdx.x < KS) w_s[threadIdx.x] = weight[threadIdx.x];
    __syncthreads();
    if (threadIdx.x == 0) {
        float s = 0.f;
        #pragma unroll
        for (int i = 0; i < KS; i++) s += w_s[i];
        wsum_s = fmaxf(s, 1e-6f);
    }
    __syncthreads();

    float cval = 0.f;
    if (m < M_BLK) {
        const float* src = role ? v : k;
        float acc = 0.f;
        const int base = m * STRIDE;
        #pragma unroll 8
        for (int kk = 0; kk < KS; kk++) {
            acc = fmaf(src[((size_t)(base + kk) * KH + kh) * D + d] + pe[kk * D + d],
                       w_s[kk], acc);
        }
        cval = acc / wsum_s;
    }

    if (role == 0) {
        // ---- K frag: pair (d, d+1) via shfl within warp ----
        const float ck1 = __shfl_down_sync(0xffffffffu, cval, 1);
        if ((d & 1) == 0) {
            const int tile = m >> 5;
            const int ni   = (m >> 3) & 3;
            const int lane = ((m & 7) << 2) | ((d >> 1) & 3);
            const int ki   = d >> 4;
            const int reg  = (d >> 3) & 1;
            const int kp   = ki >> 1;
            const int qk   = ((ki & 1) << 1) | reg;
            const int idx  = ((((kh * NTILES + tile) * 4 + ni) * 4 + kp) * 32 + lane) * 4 + qk;
            g_ckf[idx] = pack_h2(cval, ck1);
        }
    } else {
        cvs[mi][d] = cval;
    }

    __syncthreads();

    // ---- V frag: pair (m0, m0+1); written by role-1/mi-0 threads ----
    if (role == 1 && mi == 0) {
        const int m0   = blockIdx.x * 2;    // even
        const int tile = m0 >> 5;
        const int ki2  = (m0 >> 4) & 1;
        const int reg  = (m0 >> 3) & 1;
        const int lane = ((d & 7) << 2) | ((m0 >> 1) & 3);
        const int ni   = d >> 3;
        const int qv   = (ki2 << 1) | reg;
        const int idx  = (((kh * NTILES + tile) * 16 + ni) * 32 + lane) * 4 + qv;
        g_cvf[idx] = pack_h2(cvs[0][d], cvs[1][d]);
    }
}

// ---------------- kernel 2: HMMA flash attention ----------------
__global__ void __launch_bounds__(128, 4) attn_mma(
    const float* __restrict__ q, float* __restrict__ out)
{
    const int bid   = blockIdx.x;
    const int kh    = bid & 1;
    const int chunk = bid >> 1;
    const int n0    = N_TOK - NB - chunk * NB;   // heavy tokens first

    const int tid  = threadIdx.x;
    const int w    = tid >> 5;
    const int lane = tid & 31;
    const int gid  = lane >> 2;
    const int tig  = lane & 3;

    const int n      = n0 + w;
    const int Mn     = mn_of(n);
    const int Mn_max = mn_of(n0 + NB - 1);   // uniform per CTA

    if (Mn_max == 0) {
        #pragma unroll
        for (int rh = 0; rh < 2; rh++) {
            float* orow = &out[(((size_t)n * QH) + kh * G + gid + 8 * rh) * D];
            const float2 z = make_float2(0.f, 0.f);
            #pragma unroll
            for (int ni = 0; ni < 16; ni++)
                *reinterpret_cast<float2*>(&orow[ni * 8 + 2 * tig]) = z;
        }
        return;
    }

    // smem: qf (16 KB) + double-buffered K/V frag tiles (2 x 16 KB) = 48 KB
    __shared__ uint32_t qsm[NB * 1024];
    __shared__ uint32_t kbuf[2][2048];
    __shared__ uint32_t vbuf[2][2048];

    const uint32_t* kf = &g_ckf[(size_t)kh * KF_U32];
    const uint32_t* vf = &g_cvf[(size_t)kh * VF_U32];

    const int ntiles = (Mn_max + 31) >> 5;

    auto stage = [&](int tile, int slot) {
        const uint32_t sk = smem_u32(&kbuf[slot][0]) + tid * 16;
        const uint32_t sv = smem_u32(&vbuf[slot][0]) + tid * 16;
        const uint32_t* gk = kf + tile * 2048 + tid * 4;
        const uint32_t* gv = vf + tile * 2048 + tid * 4;
        #pragma unroll
        for (int i = 0; i < 4; i++) {
            cp_async16(sk + i * 2048, gk + i * 512);
            cp_async16(sv + i * 2048, gv + i * 512);
        }
    };

    // prefetch tile 0
    stage(0, 0);
    cp_commit();

    // stage Q A-fragments into warp-private smem (overlaps prefetch).
    // NOTE: scale folds log2e -> scores come out in log2 domain.
    uint32_t* myq = &qsm[w * 1024];
    #pragma unroll
    for (int ki = 0; ki < 8; ki++) {
        #pragma unroll
        for (int reg = 0; reg < 4; reg++) {
            const int g = gid + 8 * (reg & 1);
            const int c = 16 * ki + 8 * (reg >> 1) + 2 * tig;
            const float2 f = *reinterpret_cast<const float2*>(
                &q[(((size_t)n * QH) + kh * G + g) * D + c]);
            myq[ki * 128 + lane * 4 + reg] = pack_h2(f.x * QSCALE, f.y * QSCALE);
        }
    }

    float oacc[16][4];
    #pragma unroll
    for (int a = 0; a < 16; a++)
        #pragma unroll
        for (int c = 0; c < 4; c++) oacc[a][c] = 0.f;

    float rs[2] = {0.f, 0.f};

    for (int t = 0; t < ntiles; t++) {
        // prefetch next tile into alternate buffer, then wait for current
        if (t + 1 < ntiles) {
            stage(t + 1, (t + 1) & 1);
            cp_commit();
            cp_wait<1>();
        } else {
            cp_wait<0>();
        }
        __syncthreads();   // current buffer staged for all warps

        const int vcnt = Mn - (t << 5);
        if (vcnt > 0) {
            const uint32_t* kb = &kbuf[t & 1][0];
            const uint32_t* vb = &vbuf[t & 1][0];

            // ---- QK: S[16 x 32] (log2 domain) ----
            float sacc[4][4];
            #pragma unroll
            for (int a = 0; a < 4; a++)
                #pragma unroll
                for (int c = 0; c < 4; c++) sacc[a][c] = 0.f;

            #pragma unroll
            for (int kp = 0; kp < 4; kp++) {
                const uint4 a0 = *reinterpret_cast<const uint4*>(&myq[(2 * kp    ) * 128 + lane * 4]);
                const uint4 a1 = *reinterpret_cast<const uint4*>(&myq[(2 * kp + 1) * 128 + lane * 4]);
                #pragma unroll
                for (int ni = 0; ni < 4; ni++) {
                    const uint4 b = *reinterpret_cast<const uint4*>(&kb[((ni * 4 + kp) << 7) + lane * 4]);
                    mma_16816(sacc[ni], a0.x, a0.y, a0.z, a0.w, b.x, b.y);
                    mma_16816(sacc[ni], a1.x, a1.y, a1.z, a1.w, b.z, b.w);
                }
            }

            // ---- softmax: p = 2^s (shift cancels in p/sum(p)); mask invalid ----
            uint32_t pf[2][4];
            #pragma unroll
            for (int ni = 0; ni < 4; ni++) {
                const int col = ni * 8 + 2 * tig;
                const bool v0 = col     < vcnt;
                const bool v1 = col + 1 < vcnt;
                const float p0 = v0 ? exp2f(sacc[ni][0]) : 0.f;
                const float p1 = v1 ? exp2f(sacc[ni][1]) : 0.f;
                const float p2 = v0 ? exp2f(sacc[ni][2]) : 0.f;
                const float p3 = v1 ? exp2f(sacc[ni][3]) : 0.f;
                rs[0] += p0 + p1;
                rs[1] += p2 + p3;
                const int ki2 = ni >> 1, ch = ni & 1;
                pf[ki2][0 + 2 * ch] = pack_h2(p0, p1);
                pf[ki2][1 + 2 * ch] = pack_h2(p2, p3);
            }

            // ---- PV: O[16 x 128] += P @ CV ----
            #pragma unroll
            for (int ni = 0; ni < 16; ni++) {
                const uint4 b = *reinterpret_cast<const uint4*>(&vb[(ni << 7) + lane * 4]);
                mma_16816(oacc[ni], pf[0][0], pf[0][1], pf[0][2], pf[0][3], b.x, b.y);
                mma_16816(oacc[ni], pf[1][0], pf[1][1], pf[1][2], pf[1][3], b.z, b.w);
            }
        }

        __syncthreads();   // all warps done with this buffer before restaging
    }

    // ---- epilogue ----
    #pragma unroll
    for (int rh = 0; rh < 2; rh++) {
        float s = rs[rh];
        s += __shfl_xor_sync(0xffffffffu, s, 1);
        s += __shfl_xor_sync(0xffffffffu, s, 2);
        const float inv = (Mn > 0) ? (1.0f / s) : 0.f;
        float* orow = &out[(((size_t)n * QH) + kh * G + gid + 8 * rh) * D];
        #pragma unroll
        for (int ni = 0; ni < 16; ni++) {
            float2 o;
            o.x = oacc[ni][2 * rh + 0] * inv;
            o.y = oacc[ni][2 * rh + 1] * inv;
            *reinterpret_cast<float2*>(&orow[ni * 8 + 2 * tig]) = o;
        }
    }
}

// ---------------- launch ----------------
extern "C" void kernel_launch(void* const* d_in, const int* in_sizes, int n_in,
                              void* d_out, int out_size)
{
    const float* q  = (const float*)d_in[0];
    const float* k  = (const float*)d_in[1];
    const float* v  = (const float*)d_in[2];
    const float* w  = (const float*)d_in[3];
    const float* pe = (const float*)d_in[4];
    float* out = (float*)d_out;

    dim3 cgrid(256, KH);
    compress_pack_kernel<<<cgrid, 512>>>(k, v, w, pe);
    attn_mma<<<(N_TOK / NB) * KH, 128>>>(q, out);
}

// round 14
// speedup vs baseline: 1.0958x; 1.0091x over previous
#include <cuda_runtime.h>
#include <cuda_fp16.h>
#include <cstdint>
#include <math.h>

// ---------------- problem constants ----------------
constexpr int N_TOK  = 8192;
constexpr int QH     = 32;
constexpr int KH     = 2;
constexpr int G      = 16;
constexpr int D      = 128;
constexpr int KS     = 32;
constexpr int STRIDE = 16;
constexpr int M_BLK  = (N_TOK - KS) // 511
                       / STRIDE + 1;
constexpr float SM_SCALE = 0.08838834764831845f;
constexpr float LOG2E    = 1.4426950408889634f;
constexpr float QSCALE   = SM_SCALE * LOG2E;       // fold log2e into q

constexpr int NB      = 4;                  // tokens per CTA (1 per warp)
constexpr int NTILES  = 16;                 // m-tiles of 32 covering 512
constexpr int KF_U32  = NTILES * 2048;      // per kh: [tile][ni4][kp4][lane32][4]
constexpr int VF_U32  = NTILES * 2048;      // per kh: [tile][ni16][lane32][4]

// scratch (allocation-free rule: device globals)
__device__ uint32_t g_ckf[KH * KF_U32];     // QK B-fragments (half2, LDG.128-packed)
__device__ uint32_t g_cvf[KH * VF_U32];     // PV B-fragments (half2, LDG.128-packed)

__device__ __forceinline__ int mn_of(int n) {
    return (n >= KS - 1) ? ((n - (KS - 1)) / STRIDE + 1) : 0;
}
__device__ __forceinline__ uint32_t pack_h2(float a, float b) {
    __half2 h = __floats2half2_rn(a, b);
    return *reinterpret_cast<uint32_t*>(&h);
}
__device__ __forceinline__ float ex2_fast(float x) {
    float r;
    asm("ex2.approx.ftz.f32 %0, %1;" : "=f"(r) : "f"(x));
    return r;
}
__device__ __forceinline__ uint32_t smem_u32(const void* p) {
    uint32_t a;
    asm("{ .reg .u64 t; cvta.to.shared.u64 t, %1; cvt.u32.u64 %0, t; }" : "=r"(a) : "l"(p));
    return a;
}
__device__ __forceinline__ void cp_async16(uint32_t saddr, const void* gaddr) {
    asm volatile("cp.async.cg.shared.global [%0], [%1], 16;" :: "r"(saddr), "l"(gaddr));
}
__device__ __forceinline__ void cp_commit() {
    asm volatile("cp.async.commit_group;");
}
template <int N>
__device__ __forceinline__ void cp_wait() {
    asm volatile("cp.async.wait_group %0;" :: "n"(N));
}
__device__ __forceinline__ void mma_16816(float* c,
                                          uint32_t a0, uint32_t a1, uint32_t a2, uint32_t a3,
                                          uint32_t b0, uint32_t b1) {
    asm volatile("mma.sync.aligned.m16n8k16.row.col.f32.f16.f16.f32 "
                 "{%0,%1,%2,%3}, {%4,%5,%6,%7}, {%8,%9}, {%0,%1,%2,%3};"
                 : "+f"(c[0]), "+f"(c[1]), "+f"(c[2]), "+f"(c[3])
                 : "r"(a0), "r"(a1), "r"(a2), "r"(a3), "r"(b0), "r"(b1));
}

// ---------------- kernel 1: fused compression + fragment pack ----------------
// grid: (256, KH). block: 512 threads = role(2: k/v) x m-pair(2) x d(128).
__global__ void __launch_bounds__(512) compress_pack_kernel(
    const float* __restrict__ k, const float* __restrict__ v,
    const float* __restrict__ weight, const float* __restrict__ pe)
{
    const int kh   = blockIdx.y;
    const int role = threadIdx.x >> 8;        // 0 = k, 1 = v
    const int mi   = (threadIdx.x >> 7) & 1;  // which m of the pair
    const int d    = threadIdx.x & 127;
    const int m    = blockIdx.x * 2 + mi;     // 0..511 (511 = padding)

    __shared__ float w_s[KS];
    __shared__ float wsum_s;
    __shared__ float cvs[2][128];
    if (threadIdx.x < KS) w_s[threadIdx.x] = weight[threadIdx.x];
    __syncthreads();
    if (threadIdx.x == 0) {
        float s = 0.f;
        #pragma unroll
        for (int i = 0; i < KS; i++) s += w_s[i];
        wsum_s = fmaxf(s, 1e-6f);
    }
    __syncthreads();

    float cval = 0.f;
    if (m < M_BLK) {
        const float* src = role ? v : k;
        float acc = 0.f;
        const int base = m * STRIDE;
        #pragma unroll 8
        for (int kk = 0; kk < KS; kk++) {
            acc = fmaf(src[((size_t)(base + kk) * KH + kh) * D + d] + pe[kk * D + d],
                       w_s[kk], acc);
        }
        cval = acc / wsum_s;
    }

    if (role == 0) {
        // ---- K frag: pair (d, d+1) via shfl within warp ----
        const float ck1 = __shfl_down_sync(0xffffffffu, cval, 1);
        if ((d & 1) == 0) {
            const int tile = m >> 5;
            const int ni   = (m >> 3) & 3;
            const int lane = ((m & 7) << 2) | ((d >> 1) & 3);
            const int ki   = d >> 4;
            const int reg  = (d >> 3) & 1;
            const int kp   = ki >> 1;
            const int qk   = ((ki & 1) << 1) | reg;
            const int idx  = ((((kh * NTILES + tile) * 4 + ni) * 4 + kp) * 32 + lane) * 4 + qk;
            g_ckf[idx] = pack_h2(cval, ck1);
        }
    } else {
        cvs[mi][d] = cval;
    }

    __syncthreads();

    // ---- V frag: pair (m0, m0+1); written by role-1/mi-0 threads ----
    if (role == 1 && mi == 0) {
        const int m0   = blockIdx.x * 2;    // even
        const int tile = m0 >> 5;
        const int ki2  = (m0 >> 4) & 1;
        const int reg  = (m0 >> 3) & 1;
        const int lane = ((d & 7) << 2) | ((m0 >> 1) & 3);
        const int ni   = d >> 3;
        const int qv   = (ki2 << 1) | reg;
        const int idx  = (((kh * NTILES + tile) * 16 + ni) * 32 + lane) * 4 + qv;
        g_cvf[idx] = pack_h2(cvs[0][d], cvs[1][d]);
    }
}

// ---------------- kernel 2: HMMA flash attention ----------------
__global__ void __launch_bounds__(128, 4) attn_mma(
    const float* __restrict__ q, float* __restrict__ out)
{
    const int bid   = blockIdx.x;
    const int kh    = bid & 1;
    const int chunk = bid >> 1;
    const int n0    = N_TOK - NB - chunk * NB;   // heavy tokens first

    const int tid  = threadIdx.x;
    const int w    = tid >> 5;
    const int lane = tid & 31;
    const int gid  = lane >> 2;
    const int tig  = lane & 3;

    const int n      = n0 + w;
    const int Mn     = mn_of(n);
    const int Mn_max = mn_of(n0 + NB - 1);   // uniform per CTA

    if (Mn_max == 0) {
        #pragma unroll
        for (int rh = 0; rh < 2; rh++) {
            float* orow = &out[(((size_t)n * QH) + kh * G + gid + 8 * rh) * D];
            const float2 z = make_float2(0.f, 0.f);
            #pragma unroll
            for (int ni = 0; ni < 16; ni++)
                *reinterpret_cast<float2*>(&orow[ni * 8 + 2 * tig]) = z;
        }
        return;
    }

    // smem: qf (16 KB) + double-buffered K/V frag tiles (2 x 16 KB) = 48 KB
    __shared__ uint32_t qsm[NB * 1024];
    __shared__ uint32_t kbuf[2][2048];
    __shared__ uint32_t vbuf[2][2048];

    const int ntiles = (Mn_max + 31) >> 5;

    // running gmem pointers (no per-tile IMAD chains)
    const uint32_t* gk_next = &g_ckf[(size_t)kh * KF_U32] + tid * 4;
    const uint32_t* gv_next = &g_cvf[(size_t)kh * VF_U32] + tid * 4;

    auto stage = [&](int slot) {
        const uint32_t sk = smem_u32(&kbuf[slot][0]) + tid * 16;
        const uint32_t sv = smem_u32(&vbuf[slot][0]) + tid * 16;
        #pragma unroll
        for (int i = 0; i < 4; i++) {
            cp_async16(sk + i * 2048, gk_next + i * 512);
            cp_async16(sv + i * 2048, gv_next + i * 512);
        }
        gk_next += 2048;
        gv_next += 2048;
    };

    // prefetch tile 0
    stage(0);
    cp_commit();

    // stage Q A-fragments into warp-private smem (overlaps prefetch).
    // scale folds log2e -> scores come out in log2 domain.
    uint32_t* myq = &qsm[w * 1024];
    #pragma unroll
    for (int ki = 0; ki < 8; ki++) {
        #pragma unroll
        for (int reg = 0; reg < 4; reg++) {
            const int g = gid + 8 * (reg & 1);
            const int c = 16 * ki + 8 * (reg >> 1) + 2 * tig;
            const float2 f = *reinterpret_cast<const float2*>(
                &q[(((size_t)n * QH) + kh * G + g) * D + c]);
            myq[ki * 128 + lane * 4 + reg] = pack_h2(f.x * QSCALE, f.y * QSCALE);
        }
    }

    // hoisted uint4 smem views (per-lane base folded in once)
    const uint4* myq4 = reinterpret_cast<const uint4*>(myq) + lane;
    const uint4* kb4[2] = {
        reinterpret_cast<const uint4*>(&kbuf[0][0]) + lane,
        reinterpret_cast<const uint4*>(&kbuf[1][0]) + lane };
    const uint4* vb4[2] = {
        reinterpret_cast<const uint4*>(&vbuf[0][0]) + lane,
        reinterpret_cast<const uint4*>(&vbuf[1][0]) + lane };

    float oacc[16][4];
    #pragma unroll
    for (int a = 0; a < 16; a++)
        #pragma unroll
        for (int c = 0; c < 4; c++) oacc[a][c] = 0.f;

    float rs[2] = {0.f, 0.f};

    for (int t = 0; t < ntiles; t++) {
        // prefetch next tile into alternate buffer, then wait for current
        if (t + 1 < ntiles) {
            stage((t + 1) & 1);
            cp_commit();
            cp_wait<1>();
        } else {
            cp_wait<0>();
        }
        __syncthreads();   // current buffer staged for all warps

        const int vcnt = Mn - (t << 5);
        if (vcnt > 0) {
            const uint4* kb = kb4[t & 1];
            const uint4* vb = vb4[t & 1];

            // ---- QK: S[16 x 32] (log2 domain) ----
            float sacc[4][4];
            #pragma unroll
            for (int a = 0; a < 4; a++)
                #pragma unroll
                for (int c = 0; c < 4; c++) sacc[a][c] = 0.f;

            #pragma unroll
            for (int kp = 0; kp < 4; kp++) {
                const uint4 a0 = myq4[(2 * kp    ) * 32];
                const uint4 a1 = myq4[(2 * kp + 1) * 32];
                #pragma unroll
                for (int ni = 0; ni < 4; ni++) {
                    const uint4 b = kb[(ni * 4 + kp) * 32];
                    mma_16816(sacc[ni], a0.x, a0.y, a0.z, a0.w, b.x, b.y);
                    mma_16816(sacc[ni], a1.x, a1.y, a1.z, a1.w, b.z, b.w);
                }
            }

            // ---- softmax: p = 2^s via MUFU.EX2 (shift cancels in p/sum) ----
            uint32_t pf[2][4];
            #pragma unroll
            for (int ni = 0; ni < 4; ni++) {
                const int col = ni * 8 + 2 * tig;
                const bool v0 = col     < vcnt;
                const bool v1 = col + 1 < vcnt;
                const float p0 = v0 ? ex2_fast(sacc[ni][0]) : 0.f;
                const float p1 = v1 ? ex2_fast(sacc[ni][1]) : 0.f;
                const float p2 = v0 ? ex2_fast(sacc[ni][2]) : 0.f;
                const float p3 = v1 ? ex2_fast(sacc[ni][3]) : 0.f;
                rs[0] += p0 + p1;
                rs[1] += p2 + p3;
                const int ki2 = ni >> 1, ch = ni & 1;
                pf[ki2][0 + 2 * ch] = pack_h2(p0, p1);
                pf[ki2][1 + 2 * ch] = pack_h2(p2, p3);
            }

            // ---- PV: O[16 x 128] += P @ CV ----
            #pragma unroll
            for (int ni = 0; ni < 16; ni++) {
                const uint4 b = vb[ni * 32];
                mma_16816(oacc[ni], pf[0][0], pf[0][1], pf[0][2], pf[0][3], b.x, b.y);
                mma_16816(oacc[ni], pf[1][0], pf[1][1], pf[1][2], pf[1][3], b.z, b.w);
            }
        }

        __syncthreads();   // all warps done with this buffer before restaging
    }

    // ---- epilogue ----
    #pragma unroll
    for (int rh = 0; rh < 2; rh++) {
        float s = rs[rh];
        s += __shfl_xor_sync(0xffffffffu, s, 1);
        s += __shfl_xor_sync(0xffffffffu, s, 2);
        const float inv = (Mn > 0) ? (1.0f / s) : 0.f;
        float* orow = &out[(((size_t)n * QH) + kh * G + gid + 8 * rh) * D];
        #pragma unroll
        for (int ni = 0; ni < 16; ni++) {
            float2 o;
            o.x = oacc[ni][2 * rh + 0] * inv;
            o.y = oacc[ni][2 * rh + 1] * inv;
            *reinterpret_cast<float2*>(&orow[ni * 8 + 2 * tig]) = o;
        }
    }
}

// ---------------- launch ----------------
extern "C" void kernel_launch(void* const* d_in, const int* in_sizes, int n_in,
                              void* d_out, int out_size)
{
    const float* q  = (const float*)d_in[0];
    const float* k  = (const float*)d_in[1];
    const float* v  = (const float*)d_in[2];
    const float* w  = (const float*)d_in[3];
    const float* pe = (const float*)d_in[4];
    float* out = (float*)d_out;

    dim3 cgrid(256, KH);
    compress_pack_kernel<<<cgrid, 512>>>(k, v, w, pe);
    attn_mma<<<(N_TOK / NB) * KH, 128>>>(q, out);
}

// round 15
// speedup vs baseline: 1.1812x; 1.0779x over previous
#include <cuda_runtime.h>
#include <cuda_fp16.h>
#include <cstdint>
#include <math.h>

// ---------------- problem constants ----------------
constexpr int N_TOK  = 8192;
constexpr int QH     = 32;
constexpr int KH     = 2;
constexpr int G      = 16;
constexpr int D      = 128;
constexpr int KS     = 32;
constexpr int STRIDE = 16;
constexpr int M_BLK  = (N_TOK - KS) / STRIDE + 1;  // 511
constexpr float SM_SCALE = 0.08838834764831845f;
constexpr float LOG2E    = 1.4426950408889634f;
constexpr float QSCALE   = SM_SCALE * LOG2E;       // fold log2e into q

constexpr int NB      = 4;                  // tokens per CTA (1 per warp)
constexpr int NTILES  = 16;                 // m-tiles of 32 covering 512
constexpr int KF_U32  = NTILES * 2048;      // per kh: [tile][ni4][kp4][lane32][4]
constexpr int VF_U32  = NTILES * 2048;      // per kh: [tile][ni16][lane32][4]

// scratch (allocation-free rule: device globals)
__device__ uint32_t g_ckf[KH * KF_U32];     // QK B-fragments (half2, LDG.128-packed)
__device__ uint32_t g_cvf[KH * VF_U32];     // PV B-fragments (half2, LDG.128-packed)

__device__ __forceinline__ int mn_of(int n) {
    return (n >= KS - 1) ? ((n - (KS - 1)) / STRIDE + 1) : 0;
}
__device__ __forceinline__ uint32_t pack_h2(float a, float b) {
    __half2 h = __floats2half2_rn(a, b);
    return *reinterpret_cast<uint32_t*>(&h);
}
__device__ __forceinline__ float ex2_fast(float x) {
    float r;
    asm("ex2.approx.ftz.f32 %0, %1;" : "=f"(r) : "f"(x));
    return r;
}
__device__ __forceinline__ uint32_t smem_u32(const void* p) {
    uint32_t a;
    asm("{ .reg .u64 t; cvta.to.shared.u64 t, %1; cvt.u32.u64 %0, t; }" : "=r"(a) : "l"(p));
    return a;
}
__device__ __forceinline__ void cp_async16(uint32_t saddr, const void* gaddr) {
    asm volatile("cp.async.cg.shared.global [%0], [%1], 16;" :: "r"(saddr), "l"(gaddr));
}
__device__ __forceinline__ void cp_commit() {
    asm volatile("cp.async.commit_group;");
}
template <int N>
__device__ __forceinline__ void cp_wait() {
    asm volatile("cp.async.wait_group %0;" :: "n"(N));
}
__device__ __forceinline__ void mma_16816(float* c,
                                          uint32_t a0, uint32_t a1, uint32_t a2, uint32_t a3,
                                          uint32_t b0, uint32_t b1) {
    asm volatile("mma.sync.aligned.m16n8k16.row.col.f32.f16.f16.f32 "
                 "{%0,%1,%2,%3}, {%4,%5,%6,%7}, {%8,%9}, {%0,%1,%2,%3};"
                 : "+f"(c[0]), "+f"(c[1]), "+f"(c[2]), "+f"(c[3])
                 : "r"(a0), "r"(a1), "r"(a2), "r"(a3), "r"(b0), "r"(b1));
}

// ---------------- kernel 1: fused compression + fragment pack ----------------
// grid: (256, KH). block: 512 threads = role(2: k/v) x m-pair(2) x d(128).
__global__ void __launch_bounds__(512) compress_pack_kernel(
    const float* __restrict__ k, const float* __restrict__ v,
    const float* __restrict__ weight, const float* __restrict__ pe)
{
    const int kh   = blockIdx.y;
    const int role = threadIdx.x >> 8;        // 0 = k, 1 = v
    const int mi   = (threadIdx.x >> 7) & 1;  // which m of the pair
    const int d    = threadIdx.x & 127;
    const int m    = blockIdx.x * 2 + mi;     // 0..511 (511 = padding)

    __shared__ float w_s[KS];
    __shared__ float wsum_s;
    __shared__ float cvs[2][128];
    if (threadIdx.x < KS) w_s[threadIdx.x] = weight[threadIdx.x];
    __syncthreads();
    if (threadIdx.x == 0) {
        float s = 0.f;
        #pragma unroll
        for (int i = 0; i < KS; i++) s += w_s[i];
        wsum_s = fmaxf(s, 1e-6f);
    }
    __syncthreads();

    float cval = 0.f;
    if (m < M_BLK) {
        const float* src = role ? v : k;
        float acc = 0.f;
        const int base = m * STRIDE;
        #pragma unroll 8
        for (int kk = 0; kk < KS; kk++) {
            acc = fmaf(src[((size_t)(base + kk) * KH + kh) * D + d] + pe[kk * D + d],
                       w_s[kk], acc);
        }
        cval = acc / wsum_s;
    }

    if (role == 0) {
        // ---- K frag: pair (d, d+1) via shfl within warp ----
        const float ck1 = __shfl_down_sync(0xffffffffu, cval, 1);
        if ((d & 1) == 0) {
            const int tile = m >> 5;
            const int ni   = (m >> 3) & 3;
            const int lane = ((m & 7) << 2) | ((d >> 1) & 3);
            const int ki   = d >> 4;
            const int reg  = (d >> 3) & 1;
            const int kp   = ki >> 1;
            const int qk   = ((ki & 1) << 1) | reg;
            const int idx  = ((((kh * NTILES + tile) * 4 + ni) * 4 + kp) * 32 + lane) * 4 + qk;
            g_ckf[idx] = pack_h2(cval, ck1);
        }
    } else {
        cvs[mi][d] = cval;
    }

    __syncthreads();

    // ---- V frag: pair (m0, m0+1); written by role-1/mi-0 threads ----
    if (role == 1 && mi == 0) {
        const int m0   = blockIdx.x * 2;    // even
        const int tile = m0 >> 5;
        const int ki2  = (m0 >> 4) & 1;
        const int reg  = (m0 >> 3) & 1;
        const int lane = ((d & 7) << 2) | ((m0 >> 1) & 3);
        const int ni   = d >> 3;
        const int qv   = (ki2 << 1) | reg;
        const int idx  = (((kh * NTILES + tile) * 16 + ni) * 32 + lane) * 4 + qv;
        g_cvf[idx] = pack_h2(cvs[0][d], cvs[1][d]);
    }
}

// ---------------- kernel 2: HMMA flash attention, Q in registers ----------------
__global__ void __launch_bounds__(128, 3) attn_mma(
    const float* __restrict__ q, float* __restrict__ out)
{
    const int bid   = blockIdx.x;
    const int kh    = bid & 1;
    const int chunk = bid >> 1;
    const int n0    = N_TOK - NB - chunk * NB;   // heavy tokens first

    const int tid  = threadIdx.x;
    const int w    = tid >> 5;
    const int lane = tid & 31;
    const int gid  = lane >> 2;
    const int tig  = lane & 3;

    const int n      = n0 + w;
    const int Mn     = mn_of(n);
    const int Mn_max = mn_of(n0 + NB - 1);   // uniform per CTA

    if (Mn_max == 0) {
        #pragma unroll
        for (int rh = 0; rh < 2; rh++) {
            float* orow = &out[(((size_t)n * QH) + kh * G + gid + 8 * rh) * D];
            const float2 z = make_float2(0.f, 0.f);
            #pragma unroll
            for (int ni = 0; ni < 16; ni++)
                *reinterpret_cast<float2*>(&orow[ni * 8 + 2 * tig]) = z;
        }
        return;
    }

    // smem: double-buffered K/V frag tiles (2 x 16 KB) = 32 KB
    __shared__ uint32_t kbuf[2][2048];
    __shared__ uint32_t vbuf[2][2048];

    const int ntiles = (Mn_max + 31) >> 5;

    // running gmem pointers (no per-tile IMAD chains)
    const uint32_t* gk_next = &g_ckf[(size_t)kh * KF_U32] + tid * 4;
    const uint32_t* gv_next = &g_cvf[(size_t)kh * VF_U32] + tid * 4;

    auto stage = [&](int slot) {
        const uint32_t sk = smem_u32(&kbuf[slot][0]) + tid * 16;
        const uint32_t sv = smem_u32(&vbuf[slot][0]) + tid * 16;
        #pragma unroll
        for (int i = 0; i < 4; i++) {
            cp_async16(sk + i * 2048, gk_next + i * 512);
            cp_async16(sv + i * 2048, gv_next + i * 512);
        }
        gk_next += 2048;
        gv_next += 2048;
    };

    // prefetch tile 0
    stage(0);
    cp_commit();

    // ---- Q A-fragments in registers (loaded once; overlaps prefetch) ----
    // scale folds log2e -> scores come out in log2 domain.
    uint32_t qf[8][4];
    #pragma unroll
    for (int ki = 0; ki < 8; ki++) {
        #pragma unroll
        for (int reg = 0; reg < 4; reg++) {
            const int g = gid + 8 * (reg & 1);
            const int c = 16 * ki + 8 * (reg >> 1) + 2 * tig;
            const float2 f = *reinterpret_cast<const float2*>(
                &q[(((size_t)n * QH) + kh * G + g) * D + c]);
            qf[ki][reg] = pack_h2(f.x * QSCALE, f.y * QSCALE);
        }
    }

    // hoisted uint4 smem views (per-lane base folded in once)
    const uint4* kb4[2] = {
        reinterpret_cast<const uint4*>(&kbuf[0][0]) + lane,
        reinterpret_cast<const uint4*>(&kbuf[1][0]) + lane };
    const uint4* vb4[2] = {
        reinterpret_cast<const uint4*>(&vbuf[0][0]) + lane,
        reinterpret_cast<const uint4*>(&vbuf[1][0]) + lane };

    float oacc[16][4];
    #pragma unroll
    for (int a = 0; a < 16; a++)
        #pragma unroll
        for (int c = 0; c < 4; c++) oacc[a][c] = 0.f;

    float rs[2] = {0.f, 0.f};

    for (int t = 0; t < ntiles; t++) {
        // prefetch next tile into alternate buffer, then wait for current
        if (t + 1 < ntiles) {
            stage((t + 1) & 1);
            cp_commit();
            cp_wait<1>();
        } else {
            cp_wait<0>();
        }
        __syncthreads();   // current buffer staged for all warps

        const int vcnt = Mn - (t << 5);
        if (vcnt > 0) {
            const uint4* kb = kb4[t & 1];
            const uint4* vb = vb4[t & 1];

            // ---- QK: S[16 x 32] (log2 domain) ----
            float sacc[4][4];
            #pragma unroll
            for (int a = 0; a < 4; a++)
                #pragma unroll
                for (int c = 0; c < 4; c++) sacc[a][c] = 0.f;

            #pragma unroll
            for (int kp = 0; kp < 4; kp++) {
                #pragma unroll
                for (int ni = 0; ni < 4; ni++) {
                    const uint4 b = kb[(ni * 4 + kp) * 32];
                    mma_16816(sacc[ni], qf[2*kp][0],   qf[2*kp][1],   qf[2*kp][2],   qf[2*kp][3],   b.x, b.y);
                    mma_16816(sacc[ni], qf[2*kp+1][0], qf[2*kp+1][1], qf[2*kp+1][2], qf[2*kp+1][3], b.z, b.w);
                }
            }

            // ---- softmax: p = 2^s via MUFU.EX2 (shift cancels in p/sum) ----
            uint32_t pf[2][4];
            #pragma unroll
            for (int ni = 0; ni < 4; ni++) {
                const int col = ni * 8 + 2 * tig;
                const bool v0 = col     < vcnt;
                const bool v1 = col + 1 < vcnt;
                const float p0 = v0 ? ex2_fast(sacc[ni][0]) : 0.f;
                const float p1 = v1 ? ex2_fast(sacc[ni][1]) : 0.f;
                const float p2 = v0 ? ex2_fast(sacc[ni][2]) : 0.f;
                const float p3 = v1 ? ex2_fast(sacc[ni][3]) : 0.f;
                rs[0] += p0 + p1;
                rs[1] += p2 + p3;
                const int ki2 = ni >> 1, ch = ni & 1;
                pf[ki2][0 + 2 * ch] = pack_h2(p0, p1);
                pf[ki2][1 + 2 * ch] = pack_h2(p2, p3);
            }

            // ---- PV: O[16 x 128] += P @ CV ----
            #pragma unroll
            for (int ni = 0; ni < 16; ni++) {
                const uint4 b = vb[ni * 32];
                mma_16816(oacc[ni], pf[0][0], pf[0][1], pf[0][2], pf[0][3], b.x, b.y);
                mma_16816(oacc[ni], pf[1][0], pf[1][1], pf[1][2], pf[1][3], b.z, b.w);
            }
        }

        __syncthreads();   // all warps done with this buffer before restaging
    }

    // ---- epilogue ----
    #pragma unroll
    for (int rh = 0; rh < 2; rh++) {
        float s = rs[rh];
        s += __shfl_xor_sync(0xffffffffu, s, 1);
        s += __shfl_xor_sync(0xffffffffu, s, 2);
        const float inv = (Mn > 0) ? (1.0f / s) : 0.f;
        float* orow = &out[(((size_t)n * QH) + kh * G + gid + 8 * rh) * D];
        #pragma unroll
        for (int ni = 0; ni < 16; ni++) {
            float2 o;
            o.x = oacc[ni][2 * rh + 0] * inv;
            o.y = oacc[ni][2 * rh + 1] * inv;
            *reinterpret_cast<float2*>(&orow[ni * 8 + 2 * tig]) = o;
        }
    }
}

// ---------------- launch ----------------
extern "C" void kernel_launch(void* const* d_in, const int* in_sizes, int n_in,
                              void* d_out, int out_size)
{
    const float* q  = (const float*)d_in[0];
    const float* k  = (const float*)d_in[1];
    const float* v  = (const float*)d_in[2];
    const float* w  = (const float*)d_in[3];
    const float* pe = (const float*)d_in[4];
    float* out = (float*)d_out;

    dim3 cgrid(256, KH);
    compress_pack_kernel<<<cgrid, 512>>>(k, v, w, pe);
    attn_mma<<<(N_TOK / NB) * KH, 128>>>(q, out);
}

// round 17
// speedup vs baseline: 1.1928x; 1.0099x over previous
#include <cuda_runtime.h>
#include <cuda_fp16.h>
#include <cstdint>
#include <math.h>

// ---------------- problem constants ----------------
constexpr int N_TOK  = 8192;
constexpr int QH     = 32;
constexpr int KH     = 2;
constexpr int G      = 16;
constexpr int D      = 128;
constexpr int KS     = 32;
constexpr int STRIDE = 16;
constexpr int M_BLK  = (N_TOK - KS) / STRIDE + 1;  // 511
constexpr float SM_SCALE = 0.08838834764831845f;
constexpr float LOG2E    = 1.4426950408889634f;
constexpr float QSCALE   = SM_SCALE * LOG2E;       // fold log2e into q

constexpr int NB      = 8;                  // tokens per CTA (2 per warp)
constexpr int NTILES  = 16;                 // m-tiles of 32 covering 512
constexpr int KF_U32  = NTILES * 2048;      // per kh: [tile][ni4][kp4][lane32][4]
constexpr int VF_U32  = NTILES * 2048;      // per kh: [tile][ni16][lane32][4]

// scratch (allocation-free rule: device globals)
__device__ uint32_t g_ckf[KH * KF_U32];     // QK B-fragments (half2, LDG.128-packed)
__device__ uint32_t g_cvf[KH * VF_U32];     // PV B-fragments (half2, LDG.128-packed)

__device__ __forceinline__ int mn_of(int n) {
    return (n >= KS - 1) ? ((n - (KS - 1)) / STRIDE + 1) : 0;
}
__device__ __forceinline__ uint32_t pack_h2(float a, float b) {
    __half2 h = __floats2half2_rn(a, b);
    return *reinterpret_cast<uint32_t*>(&h);
}
__device__ __forceinline__ float ex2_fast(float x) {
    float r;
    asm("ex2.approx.ftz.f32 %0, %1;" : "=f"(r) : "f"(x));
    return r;
}
__device__ __forceinline__ uint32_t smem_u32(const void* p) {
    uint32_t a;
    asm("{ .reg .u64 t; cvta.to.shared.u64 t, %1; cvt.u32.u64 %0, t; }" : "=r"(a) : "l"(p));
    return a;
}
__device__ __forceinline__ void cp_async16(uint32_t saddr, const void* gaddr) {
    asm volatile("cp.async.cg.shared.global [%0], [%1], 16;" :: "r"(saddr), "l"(gaddr));
}
__device__ __forceinline__ void cp_commit() {
    asm volatile("cp.async.commit_group;");
}
template <int N>
__device__ __forceinline__ void cp_wait() {
    asm volatile("cp.async.wait_group %0;" :: "n"(N));
}
__device__ __forceinline__ void mma_16816(float* c,
                                          uint32_t a0, uint32_t a1, uint32_t a2, uint32_t a3,
                                          uint32_t b0, uint32_t b1) {
    asm volatile("mma.sync.aligned.m16n8k16.row.col.f32.f16.f16.f32 "
                 "{%0,%1,%2,%3}, {%4,%5,%6,%7}, {%8,%9}, {%0,%1,%2,%3};"
                 : "+f"(c[0]), "+f"(c[1]), "+f"(c[2]), "+f"(c[3])
                 : "r"(a0), "r"(a1), "r"(a2), "r"(a3), "r"(b0), "r"(b1));
}

// ---------------- kernel 1: fused compression + fragment pack ----------------
// grid: (256, KH). block: 512 threads = role(2: k/v) x m-pair(2) x d(128).
__global__ void __launch_bounds__(512) compress_pack_kernel(
    const float* __restrict__ k, const float* __restrict__ v,
    const float* __restrict__ weight, const float* __restrict__ pe)
{
    const int kh   = blockIdx.y;
    const int role = threadIdx.x >> 8;        // 0 = k, 1 = v
    const int mi   = (threadIdx.x >> 7) & 1;  // which m of the pair
    const int d    = threadIdx.x & 127;
    const int m    = blockIdx.x * 2 + mi;     // 0..511 (511 = padding)

    __shared__ float w_s[KS];
    __shared__ float wsum_s;
    __shared__ float cvs[2][128];
    if (threadIdx.x < KS) w_s[threadIdx.x] = weight[threadIdx.x];
    __syncthreads();
    if (threadIdx.x == 0) {
        float s = 0.f;
        #pragma unroll
        for (int i = 0; i < KS; i++) s += w_s[i];
        wsum_s = fmaxf(s, 1e-6f);
    }
    __syncthreads();

    float cval = 0.f;
    if (m < M_BLK) {
        const float* src = role ? v : k;
        float acc = 0.f;
        const int base = m * STRIDE;
        #pragma unroll 8
        for (int kk = 0; kk < KS; kk++) {
            acc = fmaf(src[((size_t)(base + kk) * KH + kh) * D + d] + pe[kk * D + d],
                       w_s[kk], acc);
        }
        cval = acc / wsum_s;
    }

    if (role == 0) {
        // ---- K frag: pair (d, d+1) via shfl within warp ----
        const float ck1 = __shfl_down_sync(0xffffffffu, cval, 1);
        if ((d & 1) == 0) {
            const int tile = m >> 5;
            const int ni   = (m >> 3) & 3;
            const int lane = ((m & 7) << 2) | ((d >> 1) & 3);
            const int ki   = d >> 4;
            const int reg  = (d >> 3) & 1;
            const int kp   = ki >> 1;
            const int qk   = ((ki & 1) << 1) | reg;
            const int idx  = ((((kh * NTILES + tile) * 4 + ni) * 4 + kp) * 32 + lane) * 4 + qk;
            g_ckf[idx] = pack_h2(cval, ck1);
        }
    } else {
        cvs[mi][d] = cval;
    }

    __syncthreads();

    // ---- V frag: pair (m0, m0+1); written by role-1/mi-0 threads ----
    if (role == 1 && mi == 0) {
        const int m0   = blockIdx.x * 2;    // even
        const int tile = m0 >> 5;
        const int ki2  = (m0 >> 4) & 1;
        const int reg  = (m0 >> 3) & 1;
        const int lane = ((d & 7) << 2) | ((m0 >> 1) & 3);
        const int ni   = d >> 3;
        const int qv   = (ki2 << 1) | reg;
        const int idx  = (((kh * NTILES + tile) * 16 + ni) * 32 + lane) * 4 + qv;
        g_cvf[idx] = pack_h2(cvs[0][d], cvs[1][d]);
    }
}

// ---------------- kernel 2: HMMA flash attention, 2 tokens/warp, Q in smem ----------------
__global__ void __launch_bounds__(128, 2) attn_mma(
    const float* __restrict__ q, float* __restrict__ out)
{
    const int bid   = blockIdx.x;
    const int kh    = bid & 1;
    const int chunk = bid >> 1;
    const int n0    = N_TOK - NB - chunk * NB;   // heavy tokens first

    const int tid  = threadIdx.x;
    const int w    = tid >> 5;
    const int lane = tid & 31;
    const int gid  = lane >> 2;
    const int tig  = lane & 3;

    const int n_t[2] = { n0 + 2 * w, n0 + 2 * w + 1 };
    const int Mn [2] = { mn_of(n_t[0]), mn_of(n_t[1]) };
    const int Mn_max = mn_of(n0 + NB - 1);   // uniform per CTA

    if (Mn_max == 0) {
        #pragma unroll
        for (int tk = 0; tk < 2; tk++) {
            #pragma unroll
            for (int rh = 0; rh < 2; rh++) {
                float* orow = &out[(((size_t)n_t[tk] * QH) + kh * G + gid + 8 * rh) * D];
                const float2 z = make_float2(0.f, 0.f);
                #pragma unroll
                for (int ni = 0; ni < 16; ni++)
                    *reinterpret_cast<float2*>(&orow[ni * 8 + 2 * tig]) = z;
            }
        }
        return;
    }

    // smem: Q frags (4 warps x 2 tokens x 4KB = 32 KB) + K/V double buffer (32 KB)
    __shared__ uint32_t qsm[NB * 1024];
    __shared__ uint32_t kbuf[2][2048];
    __shared__ uint32_t vbuf[2][2048];

    const int ntiles = (Mn_max + 31) >> 5;

    // running gmem pointers (no per-tile IMAD chains)
    const uint32_t* gk_next = &g_ckf[(size_t)kh * KF_U32] + tid * 4;
    const uint32_t* gv_next = &g_cvf[(size_t)kh * VF_U32] + tid * 4;

    auto stage = [&](int slot) {
        const uint32_t sk = smem_u32(&kbuf[slot][0]) + tid * 16;
        const uint32_t sv = smem_u32(&vbuf[slot][0]) + tid * 16;
        #pragma unroll
        for (int i = 0; i < 4; i++) {
            cp_async16(sk + i * 2048, gk_next + i * 512);
            cp_async16(sv + i * 2048, gv_next + i * 512);
        }
        gk_next += 2048;
        gv_next += 2048;
    };

    // prefetch tile 0
    stage(0);
    cp_commit();

    // ---- stage Q A-fragments for both tokens into warp-private smem ----
    // layout per warp: [tk(2)][ki(8)][lane(32)][reg(4)] u32
    uint32_t* myq = &qsm[w * 2048];
    #pragma unroll
    for (int tk = 0; tk < 2; tk++) {
        #pragma unroll
        for (int ki = 0; ki < 8; ki++) {
            #pragma unroll
            for (int reg = 0; reg < 4; reg++) {
                const int g = gid + 8 * (reg & 1);
                const int c = 16 * ki + 8 * (reg >> 1) + 2 * tig;
                const float2 f = *reinterpret_cast<const float2*>(
                    &q[(((size_t)n_t[tk] * QH) + kh * G + g) * D + c]);
                myq[tk * 1024 + ki * 128 + lane * 4 + reg] = pack_h2(f.x * QSCALE, f.y * QSCALE);
            }
        }
    }
    __syncwarp();

    // hoisted uint4 smem views (per-lane base folded in once)
    // token tk's frag (ki) lives at uint4 index tk*256 + ki*32 (+lane)
    const uint4* myq4 = reinterpret_cast<const uint4*>(myq) + lane;
    const uint4* kb4[2] = {
        reinterpret_cast<const uint4*>(&kbuf[0][0]) + lane,
        reinterpret_cast<const uint4*>(&kbuf[1][0]) + lane };
    const uint4* vb4[2] = {
        reinterpret_cast<const uint4*>(&vbuf[0][0]) + lane,
        reinterpret_cast<const uint4*>(&vbuf[1][0]) + lane };

    float oacc[2][16][4];
    #pragma unroll
    for (int tk = 0; tk < 2; tk++)
        #pragma unroll
        for (int a = 0; a < 16; a++)
            #pragma unroll
            for (int c = 0; c < 4; c++) oacc[tk][a][c] = 0.f;

    float rs[2][2] = {{0.f, 0.f}, {0.f, 0.f}};

    for (int t = 0; t < ntiles; t++) {
        // prefetch next tile into alternate buffer, then wait for current
        if (t + 1 < ntiles) {
            stage((t + 1) & 1);
            cp_commit();
            cp_wait<1>();
        } else {
            cp_wait<0>();
        }
        __syncthreads();   // current buffer staged for all warps

        const int m0 = t << 5;
        if (Mn[1] - m0 > 0) {   // token 1 has the larger Mn; skip tile if both masked
            const uint4* kb = kb4[t & 1];
            const uint4* vb = vb4[t & 1];

            // ---- QK: S[2 x 16 x 32] (log2 domain), 8 independent chains ----
            float sacc[2][4][4];
            #pragma unroll
            for (int tk = 0; tk < 2; tk++)
                #pragma unroll
                for (int a = 0; a < 4; a++)
                    #pragma unroll
                    for (int c = 0; c < 4; c++) sacc[tk][a][c] = 0.f;

            #pragma unroll
            for (int kp = 0; kp < 4; kp++) {
                const uint4 a00 = myq4[(2 * kp    ) * 32];
                const uint4 a01 = myq4[(2 * kp + 1) * 32];
                const uint4 a10 = myq4[(2 * kp    ) * 32 + 256];   // token 1: +256 uint4
                const uint4 a11 = myq4[(2 * kp + 1) * 32 + 256];
                #pragma unroll
                for (int ni = 0; ni < 4; ni++) {
                    const uint4 b = kb[(ni * 4 + kp) * 32];
                    mma_16816(sacc[0][ni], a00.x, a00.y, a00.z, a00.w, b.x, b.y);
                    mma_16816(sacc[0][ni], a01.x, a01.y, a01.z, a01.w, b.z, b.w);
                    mma_16816(sacc[1][ni], a10.x, a10.y, a10.z, a10.w, b.x, b.y);
                    mma_16816(sacc[1][ni], a11.x, a11.y, a11.z, a11.w, b.z, b.w);
                }
            }

            // ---- softmax: p = 2^s via MUFU.EX2 (shift cancels in p/sum) ----
            uint32_t pf[2][2][4];
            #pragma unroll
            for (int tk = 0; tk < 2; tk++) {
                const int vcnt = Mn[tk] - m0;
                #pragma unroll
                for (int ni = 0; ni < 4; ni++) {
                    const int col = ni * 8 + 2 * tig;
                    const bool v0 = col     < vcnt;
                    const bool v1 = col + 1 < vcnt;
                    const float p0 = v0 ? ex2_fast(sacc[tk][ni][0]) : 0.f;
                    const float p1 = v1 ? ex2_fast(sacc[tk][ni][1]) : 0.f;
                    const float p2 = v0 ? ex2_fast(sacc[tk][ni][2]) : 0.f;
                    const float p3 = v1 ? ex2_fast(sacc[tk][ni][3]) : 0.f;
                    rs[tk][0] += p0 + p1;
                    rs[tk][1] += p2 + p3;
                    const int ki2 = ni >> 1, ch = ni & 1;
                    pf[tk][ki2][0 + 2 * ch] = pack_h2(p0, p1);
                    pf[tk][ki2][1 + 2 * ch] = pack_h2(p2, p3);
                }
            }

            // ---- PV: O += P @ CV ; one vb load feeds 4 MMAs ----
            #pragma unroll
            for (int ni = 0; ni < 16; ni++) {
                const uint4 b = vb[ni * 32];
                mma_16816(oacc[0][ni], pf[0][0][0], pf[0][0][1], pf[0][0][2], pf[0][0][3], b.x, b.y);
                mma_16816(oacc[0][ni], pf[0][1][0], pf[0][1][1], pf[0][1][2], pf[0][1][3], b.z, b.w);
                mma_16816(oacc[1][ni], pf[1][0][0], pf[1][0][1], pf[1][0][2], pf[1][0][3], b.x, b.y);
                mma_16816(oacc[1][ni], pf[1][1][0], pf[1][1][1], pf[1][1][2], pf[1][1][3], b.z, b.w);
            }
        }

        __syncthreads();   // all warps done with this buffer before restaging
    }

    // ---- epilogue ----
    #pragma unroll
    for (int tk = 0; tk < 2; tk++) {
        #pragma unroll
        for (int rh = 0; rh < 2; rh++) {
            float s = rs[tk][rh];
            s += __shfl_xor_sync(0xffffffffu, s, 1);
            s += __shfl_xor_sync(0xffffffffu, s, 2);
            const float inv = (Mn[tk] > 0) ? (1.0f / s) : 0.f;
            float* orow = &out[(((size_t)n_t[tk] * QH) + kh * G + gid + 8 * rh) * D];
            #pragma unroll
            for (int ni = 0; ni < 16; ni++) {
                float2 o;
                o.x = oacc[tk][ni][2 * rh + 0] * inv;
                o.y = oacc[tk][ni][2 * rh + 1] * inv;
                *reinterpret_cast<float2*>(&orow[ni * 8 + 2 * tig]) = o;
            }
        }
    }
}

// ---------------- launch ----------------
extern "C" void kernel_launch(void* const* d_in, const int* in_sizes, int n_in,
                              void* d_out, int out_size)
{
    const float* q  = (const float*)d_in[0];
    const float* k  = (const float*)d_in[1];
    const float* v  = (const float*)d_in[2];
    const float* w  = (const float*)d_in[3];
    const float* pe = (const float*)d_in[4];
    float* out = (float*)d_out;

    dim3 cgrid(256, KH);
    compress_pack_kernel<<<cgrid, 512>>>(k, v, w, pe);
    attn_mma<<<(N_TOK / NB) * KH, 128>>>(q, out);
}